// round 3
// baseline (speedup 1.0000x reference)
#include <cuda_runtime.h>
#include <cstdint>

// out[b, j] = relu( sum_d x[b,d] * (gamma*W3[j,d] + W4[j,d]) )
// softmax over a size-1 axis is identically 1 -> attention collapses, W1/W2 dead,
// and the two reshapes are flat-order-preserving, so res == x @ W3^T exactly.

#define B_ROWS   262144
#define DICTD    20
#define JCOLS    200
#define GROUPS   8                         // row-groups per tile
#define RPG      4                         // rows per group
#define CPT      2                         // columns per thread
#define CPAIRS   (JCOLS / CPT)             // 100 col-pairs
#define TILE_ROWS (GROUPS * RPG)           // 32
#define NTILES   (B_ROWS / TILE_ROWS)      // 8192
#define NTHREADS (GROUPS * CPAIRS)         // 800 = 25 full warps
#define NBLOCKS  148

typedef unsigned long long ull;

__device__ __forceinline__ ull pack2(float lo, float hi) {
    ull r;
    asm("mov.b64 %0, {%1, %2};" : "=l"(r) : "f"(lo), "f"(hi));
    return r;
}
__device__ __forceinline__ void unpack2(ull v, float& lo, float& hi) {
    asm("mov.b64 {%0, %1}, %2;" : "=f"(lo), "=f"(hi) : "l"(v));
}
// Packed dual fp32 FMA (sm_100+). ptxas never emits this from C++; only via PTX.
// Scalar FFMA (3-reg) runs at half the fp32 datapath rate; f32x2 reaches full rate.
__device__ __forceinline__ ull fma2(ull a, ull b, ull c) {
    ull d;
    asm("fma.rn.f32x2 %0, %1, %2, %3;" : "=l"(d) : "l"(a), "l"(b), "l"(c));
    return d;
}

__global__ void __launch_bounds__(NTHREADS, 1)
fused_relu_gemm_kernel(const float* __restrict__ x,
                       const float* __restrict__ W3,
                       const float* __restrict__ W4,
                       const float* __restrict__ gamma,
                       float* __restrict__ out)
{
    // x staged DUPLICATED as (x,x) f32x2: xsd[group][d][row_in_group]
    // -> one ulonglong2 (LDS.128) yields 2 rows' duplicated x_d.
    __shared__ __align__(16) ull xsd[GROUPS][DICTD][RPG];

    const int tid = threadIdx.x;
    const int g   = tid / CPAIRS;          // 0..7   row-group
    const int cp  = tid % CPAIRS;          // 0..99  column pair (j = 2cp, 2cp+1)
    const int j0  = cp * CPT;

    // ---- one-time: effective weights for the 2 owned columns, as f32x2 ----
    const float gm = __ldg(gamma);
    ull wd[DICTD];
#pragma unroll
    for (int d = 0; d < DICTD; d++) {
        float wa = fmaf(gm, __ldg(&W3[(j0 + 0) * DICTD + d]), __ldg(&W4[(j0 + 0) * DICTD + d]));
        float wb = fmaf(gm, __ldg(&W3[(j0 + 1) * DICTD + d]), __ldg(&W4[(j0 + 1) * DICTD + d]));
        wd[d] = pack2(wa, wb);
    }

    // staging role: threads 0..639 each fetch one float of the 32x20 tile
    const int  sr     = tid / DICTD;               // row in tile (valid < 32)
    const int  sd     = tid % DICTD;
    const bool stager = (tid < TILE_ROWS * DICTD); // tid < 640

    int tile = blockIdx.x;
    float val = 0.0f;
    if (stager)
        val = x[(tile * TILE_ROWS + sr) * DICTD + sd];

    const ulonglong2* xrow = reinterpret_cast<const ulonglong2*>(&xsd[g][0][0]);

    for (; tile < NTILES; tile += NBLOCKS) {
        if (stager)
            xsd[sr / RPG][sd][sr % RPG] = pack2(val, val);   // one STS.64
        __syncthreads();

        // prefetch next tile into registers while computing this one
        const int ntile = tile + NBLOCKS;
        if (stager && ntile < NTILES)
            val = x[(ntile * TILE_ROWS + sr) * DICTD + sd];

        // ---- core: 4 rows x 2 columns per thread ----
        ull a0 = 0ULL, a1 = 0ULL, a2 = 0ULL, a3 = 0ULL;
#pragma unroll
        for (int d = 0; d < DICTD; d++) {
            ulonglong2 lo = xrow[d * 2 + 0];   // dup x for rows 0,1
            ulonglong2 hi = xrow[d * 2 + 1];   // dup x for rows 2,3
            a0 = fma2(lo.x, wd[d], a0);
            a1 = fma2(lo.y, wd[d], a1);
            a2 = fma2(hi.x, wd[d], a2);
            a3 = fma2(hi.y, wd[d], a3);
        }

        // ---- relu + coalesced STG.64 (lanes: consecutive col-pairs) ----
        const int rowbase = tile * TILE_ROWS + g * RPG;
        float f0, f1;
        float2* o;
        unpack2(a0, f0, f1);
        o = reinterpret_cast<float2*>(&out[(rowbase + 0) * JCOLS + j0]);
        *o = make_float2(fmaxf(f0, 0.0f), fmaxf(f1, 0.0f));
        unpack2(a1, f0, f1);
        o = reinterpret_cast<float2*>(&out[(rowbase + 1) * JCOLS + j0]);
        *o = make_float2(fmaxf(f0, 0.0f), fmaxf(f1, 0.0f));
        unpack2(a2, f0, f1);
        o = reinterpret_cast<float2*>(&out[(rowbase + 2) * JCOLS + j0]);
        *o = make_float2(fmaxf(f0, 0.0f), fmaxf(f1, 0.0f));
        unpack2(a3, f0, f1);
        o = reinterpret_cast<float2*>(&out[(rowbase + 3) * JCOLS + j0]);
        *o = make_float2(fmaxf(f0, 0.0f), fmaxf(f1, 0.0f));

        __syncthreads();   // everyone done reading xsd before next stage
    }
}

extern "C" void kernel_launch(void* const* d_in, const int* in_sizes, int n_in,
                              void* d_out, int out_size)
{
    // metadata order: x, W1, W2, W3, W4, gamma  (W1/W2 mathematically dead)
    const float* x     = (const float*)d_in[0];
    const float* W3    = (const float*)d_in[3];
    const float* W4    = (const float*)d_in[4];
    const float* gamma = (const float*)d_in[5];
    float*       out   = (float*)d_out;

    fused_relu_gemm_kernel<<<NBLOCKS, NTHREADS>>>(x, W3, W4, gamma, out);
}

// round 5
// speedup vs baseline: 1.2365x; 1.2365x over previous
#include <cuda_runtime.h>
#include <cstdint>

// out[b, j] = relu( sum_d x[b,d] * (gamma*W3[j,d] + W4[j,d]) )
// softmax over size-1 axis == 1 -> attention collapses; W1/W2 dead; reshapes are
// flat-order-preserving so res == x @ W3^T exactly.
//
// R3 lesson (ncu): L1 return BW is charged per LANE-BYTE (128B/cyc/SM); broadcast
// LDS.128 = 4 wavefronts. So maximize MACs per LDS byte: load x UNduplicated,
// duplicate in-register (ALU), reuse across 4 columns -> 1 B/MAC (was 2 B/MAC).

#define B_ROWS    262144
#define DICTD     20
#define JCOLS     200
#define RPT       8                       // rows per thread
#define CPT       4                       // cols per thread
#define TILE_ROWS 32
#define NGROUPS   (TILE_ROWS / RPT)       // 4 row-groups
#define NQUADS    (JCOLS / CPT)           // 50 col-quads
#define NTHREADS  (NGROUPS * NQUADS)      // 200
#define NTILES    (B_ROWS / TILE_ROWS)    // 8192
#define NBLOCKS   296                     // 2 per SM (148 SMs)
#define GSTRIDE   (DICTD * RPT + 4)       // 164 floats: +16B pad de-conflicts groups

typedef unsigned long long ull;

__device__ __forceinline__ ull pack2(float lo, float hi) {
    ull r;
    asm("mov.b64 %0, {%1, %2};" : "=l"(r) : "f"(lo), "f"(hi));
    return r;
}
// Packed dual fp32 FMA (sm_100+); full-rate fp32 datapath, 2 MACs/inst.
__device__ __forceinline__ ull fma2(ull a, ull b, ull c) {
    ull d;
    asm("fma.rn.f32x2 %0, %1, %2, %3;" : "=l"(d) : "l"(a), "l"(b), "l"(c));
    return d;
}

__global__ void __launch_bounds__(NTHREADS, 2)
fused_relu_gemm_kernel(const float* __restrict__ x,
                       const float* __restrict__ W3,
                       const float* __restrict__ W4,
                       const float* __restrict__ gamma,
                       float* __restrict__ out)
{
    // xs[group][d][row 0..7] (un-duplicated), group stride padded to 164 floats
    __shared__ __align__(16) float xs[NGROUPS * GSTRIDE];

    const int tid = threadIdx.x;
    const int g   = tid / NQUADS;          // 0..3  row-group (8 rows)
    const int q   = tid % NQUADS;          // 0..49 col-quad
    const int j0  = q * CPT;

    // ---- one-time: effective weights for 4 owned columns as f32x2 pairs ----
    const float gm = __ldg(gamma);
    ull w0[DICTD], w1[DICTD];              // (j0,j0+1) and (j0+2,j0+3)
#pragma unroll
    for (int d = 0; d < DICTD; d++) {
        float a = fmaf(gm, __ldg(&W3[(j0 + 0) * DICTD + d]), __ldg(&W4[(j0 + 0) * DICTD + d]));
        float b = fmaf(gm, __ldg(&W3[(j0 + 1) * DICTD + d]), __ldg(&W4[(j0 + 1) * DICTD + d]));
        float c = fmaf(gm, __ldg(&W3[(j0 + 2) * DICTD + d]), __ldg(&W4[(j0 + 2) * DICTD + d]));
        float e = fmaf(gm, __ldg(&W3[(j0 + 3) * DICTD + d]), __ldg(&W4[(j0 + 3) * DICTD + d]));
        w0[d] = pack2(a, b);
        w1[d] = pack2(c, e);
    }

    // ---- staging role: 160 threads each fetch one float4 of the 32x20 tile ----
    const bool stager = (tid < TILE_ROWS * DICTD / 4);   // tid < 160
    const float4* x4 = reinterpret_cast<const float4*>(x);
    // flat float index f = tid*4 .. tid*4+3 : one row (20 % 4 == 0), 4 consecutive d
    const int r_t = (tid * 4) / DICTD;                   // row in tile
    const int d0  = (tid * 4) % DICTD;
    float* sdst = &xs[(r_t / RPT) * GSTRIDE + (r_t % RPT) + d0 * RPT];

    int tile = blockIdx.x;
    float4 v = make_float4(0.f, 0.f, 0.f, 0.f);
    if (stager) v = x4[tile * (TILE_ROWS * DICTD / 4) + tid];

    const float* base = &xs[g * GSTRIDE];

    for (; tile < NTILES; tile += NBLOCKS) {
        if (stager) {                                    // 4 x STS.32, stride 8 floats
            sdst[0 * RPT] = v.x;
            sdst[1 * RPT] = v.y;
            sdst[2 * RPT] = v.z;
            sdst[3 * RPT] = v.w;
        }
        __syncthreads();

        // prefetch next tile while computing this one
        const int ntile = tile + NBLOCKS;
        if (stager && ntile < NTILES)
            v = x4[ntile * (TILE_ROWS * DICTD / 4) + tid];

        // ---- core: 8 rows x 4 cols; 2 LDS.128 + 8 pack + 16 fma2 per d ----
        ull a00 = 0, a01 = 0, a10 = 0, a11 = 0, a20 = 0, a21 = 0, a30 = 0, a31 = 0;
        ull a40 = 0, a41 = 0, a50 = 0, a51 = 0, a60 = 0, a61 = 0, a70 = 0, a71 = 0;
#pragma unroll
        for (int d = 0; d < DICTD; d++) {
            const float4 lo = *reinterpret_cast<const float4*>(base + d * RPT);      // rows 0-3
            const float4 hi = *reinterpret_cast<const float4*>(base + d * RPT + 4);  // rows 4-7
            ull t;
            t = pack2(lo.x, lo.x); a00 = fma2(t, w0[d], a00); a01 = fma2(t, w1[d], a01);
            t = pack2(lo.y, lo.y); a10 = fma2(t, w0[d], a10); a11 = fma2(t, w1[d], a11);
            t = pack2(lo.z, lo.z); a20 = fma2(t, w0[d], a20); a21 = fma2(t, w1[d], a21);
            t = pack2(lo.w, lo.w); a30 = fma2(t, w0[d], a30); a31 = fma2(t, w1[d], a31);
            t = pack2(hi.x, hi.x); a40 = fma2(t, w0[d], a40); a41 = fma2(t, w1[d], a41);
            t = pack2(hi.y, hi.y); a50 = fma2(t, w0[d], a50); a51 = fma2(t, w1[d], a51);
            t = pack2(hi.z, hi.z); a60 = fma2(t, w0[d], a60); a61 = fma2(t, w1[d], a61);
            t = pack2(hi.w, hi.w); a70 = fma2(t, w0[d], a70); a71 = fma2(t, w1[d], a71);
        }

        // ---- relu + coalesced STG.128 (lanes = consecutive quads) ----
        const int rowbase = tile * TILE_ROWS + g * RPT;
#define EMIT(r, p0, p1)                                                          \
        {                                                                        \
            float2 f0 = *reinterpret_cast<float2*>(&p0);                         \
            float2 f1 = *reinterpret_cast<float2*>(&p1);                         \
            float4 o = make_float4(fmaxf(f0.x, 0.f), fmaxf(f0.y, 0.f),           \
                                   fmaxf(f1.x, 0.f), fmaxf(f1.y, 0.f));          \
            *reinterpret_cast<float4*>(&out[(rowbase + (r)) * JCOLS + j0]) = o;  \
        }
        EMIT(0, a00, a01) EMIT(1, a10, a11) EMIT(2, a20, a21) EMIT(3, a30, a31)
        EMIT(4, a40, a41) EMIT(5, a50, a51) EMIT(6, a60, a61) EMIT(7, a70, a71)
#undef EMIT

        __syncthreads();   // all reads of xs done before next stage
    }
}

extern "C" void kernel_launch(void* const* d_in, const int* in_sizes, int n_in,
                              void* d_out, int out_size)
{
    // metadata order: x, W1, W2, W3, W4, gamma  (W1/W2 mathematically dead)
    const float* x     = (const float*)d_in[0];
    const float* W3    = (const float*)d_in[3];
    const float* W4    = (const float*)d_in[4];
    const float* gamma = (const float*)d_in[5];
    float*       out   = (float*)d_out;

    fused_relu_gemm_kernel<<<NBLOCKS, NTHREADS>>>(x, W3, W4, gamma, out);
}